// round 9
// baseline (speedup 1.0000x reference)
#include <cuda_runtime.h>
#include <cuda_bf16.h>
#include <cstdint>

#define N_ROWS   16384
#define DIN      128
#define DOUT     64
#define KDIM     16384
#define MIN_NORM 1e-15f
#define ART_CLAMP (1.0f - 1e-7f)
#define MAXNORM  (1.0f - 4e-3f)

#define TK      64            // k per chunk
#define NCH     (KDIM / TK)   // 256 chunks
#define BP8     80            // int8 B smem row pitch (64B data + 16B pad)
#define BTILE8  (64 * BP8)    // 5120 B per limb tile (n64 x k64 s8)
#define STAGE8  (2 * BTILE8)  // hi + lo = 10240
#define BSTAGES 3
#define SMEM_B_BYTES (BSTAGES * STAGE8)   // 30720

#define Q16MAX   32511                    // 127*256 + 127 (keeps limbs in s8/u8 range)
#define SA_SCALE 532660224.0f             // 32511 * 16384  (A in [0, 1/16384))

// Tangent matrix (fp32, K-major transposed) + int8 limb matrices
__device__ float       g_T [DOUT * KDIM];
__device__ signed char g_Bh[DOUT * KDIM];   // high limb (s8, [-127,127])
__device__ signed char g_Bl[DOUT * KDIM];   // low  limb (s8, [-128,127], zero-mean)
__device__ int         g_absmaxBits;        // max |tangent| as float bits

// ---------------------------------------------------------------------------
// helpers
// ---------------------------------------------------------------------------
__device__ __forceinline__ uint32_t smem_u32(const void* p) {
    uint32_t a;
    asm("{ .reg .u64 t; cvta.to.shared.u64 t, %1; cvt.u32.u64 %0, t; }" : "=r"(a) : "l"(p));
    return a;
}
__device__ __forceinline__ void cp_async16(uint32_t dst, const void* src) {
    asm volatile(
        "{ .reg .u64 gp; cvta.to.global.u64 gp, %1;"
        " cp.async.cg.shared.global [%0], [gp], 16; }"
        :: "r"(dst), "l"(src) : "memory");
}
#define CP_COMMIT()  asm volatile("cp.async.commit_group;" ::: "memory")
#define CP_WAIT1()   asm volatile("cp.async.wait_group 1;" ::: "memory")
#define CP_WAIT0()   asm volatile("cp.async.wait_group 0;" ::: "memory")

__device__ __forceinline__ void ldsm4(uint32_t addr, uint32_t* r) {
    asm volatile("ldmatrix.sync.aligned.m8n8.x4.shared.b16 {%0,%1,%2,%3}, [%4];"
                 : "=r"(r[0]), "=r"(r[1]), "=r"(r[2]), "=r"(r[3]) : "r"(addr));
}
// D(s32) += A(u8) * B(s8)
__device__ __forceinline__ void mma_u8s8(int* c, const uint32_t* a, uint32_t b0, uint32_t b1) {
    asm volatile(
        "mma.sync.aligned.m16n8k32.row.col.s32.u8.s8.s32 "
        "{%0,%1,%2,%3}, {%4,%5,%6,%7}, {%8,%9}, {%0,%1,%2,%3};"
        : "+r"(c[0]), "+r"(c[1]), "+r"(c[2]), "+r"(c[3])
        : "r"(a[0]), "r"(a[1]), "r"(a[2]), "r"(a[3]), "r"(b0), "r"(b1));
}
// D(s32) += A(s8) * B(s8)
__device__ __forceinline__ void mma_s8s8(int* c, const uint32_t* a, uint32_t b0, uint32_t b1) {
    asm volatile(
        "mma.sync.aligned.m16n8k32.row.col.s32.s8.s8.s32 "
        "{%0,%1,%2,%3}, {%4,%5,%6,%7}, {%8,%9}, {%0,%1,%2,%3};"
        : "+r"(c[0]), "+r"(c[1]), "+r"(c[2]), "+r"(c[3])
        : "r"(a[0]), "r"(a[1]), "r"(a[2]), "r"(a[3]), "r"(b0), "r"(b1));
}
__device__ __forceinline__ float wsum(float v) {
#pragma unroll
    for (int o = 16; o > 0; o >>= 1) v += __shfl_xor_sync(0xffffffffu, v, o);
    return v;
}
__device__ __forceinline__ float wmax(float v) {
#pragma unroll
    for (int o = 16; o > 0; o >>= 1) v = fmaxf(v, __shfl_xor_sync(0xffffffffu, v, o));
    return v;
}

// ---------------------------------------------------------------------------
__global__ void zero_kernel() { g_absmaxBits = 0; }

// ---------------------------------------------------------------------------
// Kernel A: hyperbolic transform -> tangent (fp32, K-major) + global absmax.
// ---------------------------------------------------------------------------
__global__ __launch_bounds__(256) void transform_kernel(
    const float* __restrict__ X,
    const float* __restrict__ W,
    const float* __restrict__ bias)
{
    __shared__ float2 sW2[DIN * 32];   // [k][t] = (W[k][t], W[k][t+32])

    const int tid = threadIdx.x;
    for (int i = tid; i < DIN * 32; i += 256) {
        const int k = i >> 5, t = i & 31;
        sW2[i] = make_float2(W[k * DOUT + t], W[k * DOUT + t + 32]);
    }
    __syncthreads();

    const int w    = tid >> 5;
    const int lane = tid & 31;
    const int row  = blockIdx.x * 8 + w;

    // hyp_bias = proj(expmap0(bias))
    float b1 = bias[lane], b2v = bias[lane + 32];
    float b2 = wsum(b1 * b1 + b2v * b2v);
    float bn = fmaxf(sqrtf(b2), MIN_NORM);
    float tb = tanhf(bn) / bn;
    float e1 = tb * b1, e2v = tb * b2v;
    float e2 = wsum(e1 * e1 + e2v * e2v);
    float en = fmaxf(sqrtf(e2), MIN_NORM);
    float sc = (en > MAXNORM) ? (MAXNORM / en) : 1.f;
    float h1 = e1 * sc, h2v = e2v * sc;
    float h2 = wsum(h1 * h1 + h2v * h2v);

    float xr[4];
#pragma unroll
    for (int j = 0; j < 4; ++j) xr[j] = X[(size_t)row * DIN + lane + 32 * j];
    float x2 = wsum(xr[0] * xr[0] + xr[1] * xr[1] + xr[2] * xr[2] + xr[3] * xr[3]);

    float ma = 0.f, mb = 0.f;
#pragma unroll
    for (int j = 0; j < 4; ++j) {
#pragma unroll
        for (int l = 0; l < 32; ++l) {
            const float xv = __shfl_sync(0xffffffffu, xr[j], l);
            const float2 wv = sW2[(j * 32 + l) * 32 + lane];
            ma = fmaf(xv, wv.x, ma);
            mb = fmaf(xv, wv.y, mb);
        }
    }

    float m2 = wsum(ma * ma + mb * mb);
    float xn = fmaxf(sqrtf(x2), MIN_NORM);
    float mn = fmaxf(sqrtf(m2), MIN_NORM);

    float artx = atanhf(fminf(xn, ART_CLAMP));
    float tf   = tanhf(mn / xn * artx) / mn;
    float r1 = tf * ma, r2v = tf * mb;
    if (m2 == 0.f) { r1 = 0.f; r2v = 0.f; }

    float r2 = wsum(r1 * r1 + r2v * r2v);
    float rh = wsum(r1 * h1 + r2v * h2v);
    float al  = 1.f + 2.f * rh + h2;
    float den = fmaxf(1.f + 2.f * rh + r2 * h2, MIN_NORM);
    float p1  = (al * r1  + (1.f - r2) * h1)  / den;
    float p2v = (al * r2v + (1.f - r2) * h2v) / den;

    float p2 = wsum(p1 * p1 + p2v * p2v);
    float pn = fmaxf(sqrtf(p2), MIN_NORM);
    if (pn > MAXNORM) {
        float s = MAXNORM / pn;
        p1 *= s; p2v *= s; pn = MAXNORM;
    }

    float lf = atanhf(fminf(pn, ART_CLAMP)) / pn;
    float t1 = lf * p1, t2 = lf * p2v;

    g_T[(size_t)lane * KDIM + row]        = t1;
    g_T[(size_t)(lane + 32) * KDIM + row] = t2;

    float mloc = wmax(fmaxf(fabsf(t1), fabsf(t2)));
    if (lane == 0) atomicMax(&g_absmaxBits, __float_as_int(mloc));
}

// ---------------------------------------------------------------------------
// Kernel A2: quantize tangent to int16, centered split to s8 limbs:
//   b16 = clamp(rni(t*sB), +-Q16MAX); bl = ((b16+128)&255)-128; bh = (b16-bl)>>8
// ---------------------------------------------------------------------------
__global__ __launch_bounds__(256) void quantB_kernel()
{
    const float am = __int_as_float(g_absmaxBits);
    const float sB = (float)Q16MAX / fmaxf(am, 1e-30f);

    const int idx = (blockIdx.x * 256 + threadIdx.x) * 4;
    const float4 v = *(const float4*)&g_T[idx];

    int b[4];
    b[0] = max(min(__float2int_rn(v.x * sB), Q16MAX), -Q16MAX);
    b[1] = max(min(__float2int_rn(v.y * sB), Q16MAX), -Q16MAX);
    b[2] = max(min(__float2int_rn(v.z * sB), Q16MAX), -Q16MAX);
    b[3] = max(min(__float2int_rn(v.w * sB), Q16MAX), -Q16MAX);

    char4 hi, lo;
    int l0 = ((b[0] + 128) & 255) - 128;
    int l1 = ((b[1] + 128) & 255) - 128;
    int l2 = ((b[2] + 128) & 255) - 128;
    int l3 = ((b[3] + 128) & 255) - 128;
    lo.x = (char)l0; lo.y = (char)l1; lo.z = (char)l2; lo.w = (char)l3;
    hi.x = (char)((b[0] - l0) >> 8); hi.y = (char)((b[1] - l1) >> 8);
    hi.z = (char)((b[2] - l2) >> 8); hi.w = (char)((b[3] - l3) >> 8);

    *(char4*)&g_Bh[idx] = hi;
    *(char4*)&g_Bl[idx] = lo;
}

// ---------------------------------------------------------------------------
// Kernel B: out = relu(A @ T) via int8 IMMA m16n8k32, centered-limb split:
//   a16*b16 = 65536*ah*bh + 256*(ah*bl + al*bh) + al*bl(dropped, zero-mean)
// 128 CTAs x 256 thr (8 warps m16 each), M128/N64/K-chunk 64. R4 pipeline.
// ---------------------------------------------------------------------------
struct APre { float4 v[8]; };   // [r*4 + kf]: rows {g, g+8}, kf 0..3 (k16 steps)

__device__ __forceinline__ void ldA(APre& p, const float* pa0, const float* pa8, int kb) {
#pragma unroll
    for (int kf = 0; kf < 4; ++kf) {
        p.v[kf]     = *(const float4*)(pa0 + kb + kf * 16);
        p.v[4 + kf] = *(const float4*)(pa8 + kb + kf * 16);
    }
}

// quantize one float4 to packed ah (u8x4, byte0 of each) / al (s8x4)
__device__ __forceinline__ void quantA4(float4 v, uint32_t& ahP, uint32_t& alP) {
    int q0 = min(__float2int_rn(v.x * SA_SCALE), Q16MAX);
    int q1 = min(__float2int_rn(v.y * SA_SCALE), Q16MAX);
    int q2 = min(__float2int_rn(v.z * SA_SCALE), Q16MAX);
    int q3 = min(__float2int_rn(v.w * SA_SCALE), Q16MAX);
    int l0 = ((q0 + 128) & 255) - 128;
    int l1 = ((q1 + 128) & 255) - 128;
    int l2 = ((q2 + 128) & 255) - 128;
    int l3 = ((q3 + 128) & 255) - 128;
    int h0 = (q0 - l0) >> 8, h1 = (q1 - l1) >> 8;
    int h2 = (q2 - l2) >> 8, h3 = (q3 - l3) >> 8;
    uint32_t hA = __byte_perm((uint32_t)h0, (uint32_t)h1, 0x0040);
    uint32_t hB = __byte_perm((uint32_t)h2, (uint32_t)h3, 0x0040);
    ahP = __byte_perm(hA, hB, 0x5410);
    uint32_t lA = __byte_perm((uint32_t)l0, (uint32_t)l1, 0x0040);
    uint32_t lB = __byte_perm((uint32_t)l2, (uint32_t)l3, 0x0040);
    alP = __byte_perm(lA, lB, 0x5410);
}

__global__ __launch_bounds__(256, 1) void gemm_kernel(
    const float* __restrict__ A,
    float* __restrict__ out)
{
    extern __shared__ __align__(128) char sB[];   // [stage][hi(5120) | lo(5120)]

    const int tid  = threadIdx.x;
    const int w    = tid >> 5;
    const int lane = tid & 31;
    const int g    = lane >> 2;
    const int t4   = lane & 3;
    const int m0   = blockIdx.x * 128;

    const float* pa0 = A + (size_t)(m0 + w * 16 + g) * KDIM + 4 * t4;
    const float* pa8 = pa0 + (size_t)8 * KDIM;

    // cp.async mapping: per limb, thread -> row tid>>2, 16B chunk tid&3
    const int brow = tid >> 2;
    const int bq   = tid & 3;
    const uint32_t sb0 = smem_u32(sB);
    const uint32_t dOffH = (uint32_t)(brow * BP8 + bq * 16);
    const uint32_t dOffL = dOffH + (uint32_t)BTILE8;
    const signed char* srcH = &g_Bh[(size_t)brow * KDIM + bq * 16];
    const signed char* srcL = &g_Bl[(size_t)brow * KDIM + bq * 16];

    const uint32_t lmOff = (uint32_t)((lane & 7) * BP8 + (lane >> 3) * 16);

    int accP1[8][4], accP23[8][4];
#pragma unroll
    for (int i = 0; i < 8; ++i)
#pragma unroll
        for (int j = 0; j < 4; ++j) { accP1[i][j] = 0; accP23[i][j] = 0; }

    // prologue: B stages 0,1 ; A chunk 0
#pragma unroll
    for (int s = 0; s < 2; ++s) {
        const int kb = s * TK;
        const uint32_t db = sb0 + (uint32_t)(s * STAGE8);
        cp_async16(db + dOffH, srcH + kb);
        cp_async16(db + dOffL, srcL + kb);
        CP_COMMIT();
    }

    APre pre;
    ldA(pre, pa0, pa8, 0);

    for (int i = 0; i < NCH; ++i) {
        const int s = i % BSTAGES;

        if (i < NCH - 1) { CP_WAIT1(); } else { CP_WAIT0(); }
        __syncthreads();

        if (i + 2 < NCH) {
            const int kb = (i + 2) * TK;
            const uint32_t db = sb0 + (uint32_t)(((i + 2) % BSTAGES) * STAGE8);
            cp_async16(db + dOffH, srcH + kb);
            cp_async16(db + dOffL, srcL + kb);
            CP_COMMIT();
        }

        // quantize A chunk i (regs loaded last iter), then prefetch chunk i+1
        uint32_t ahP[8], alP[8];
#pragma unroll
        for (int j = 0; j < 8; ++j) quantA4(pre.v[j], ahP[j], alP[j]);
        if (i + 1 < NCH) ldA(pre, pa0, pa8, (i + 1) * TK);

        // fragments per k32 product j: a0=(g,k0) a1=(g+8,k0) a2=(g,k16) a3=(g+8,k16)
        uint32_t aH[2][4], aL[2][4];
#pragma unroll
        for (int j = 0; j < 2; ++j) {
            aH[j][0] = ahP[2 * j];     aH[j][1] = ahP[4 + 2 * j];
            aH[j][2] = ahP[2 * j + 1]; aH[j][3] = ahP[4 + 2 * j + 1];
            aL[j][0] = alP[2 * j];     aL[j][1] = alP[4 + 2 * j];
            aL[j][2] = alP[2 * j + 1]; aL[j][3] = alP[4 + 2 * j + 1];
        }

        const uint32_t bhBase = sb0 + (uint32_t)(s * STAGE8) + lmOff;
        const uint32_t blBase = bhBase + (uint32_t)BTILE8;

        uint32_t bfr[8][4];
        // hi limb of B: P1 (ah*bh) and P3 (al*bh)
#pragma unroll
        for (int nt = 0; nt < 8; ++nt)
            ldsm4(bhBase + (uint32_t)(nt * 8 * BP8), bfr[nt]);
#pragma unroll
        for (int nt = 0; nt < 8; ++nt) mma_u8s8(accP1[nt],  aH[0], bfr[nt][0], bfr[nt][1]);
#pragma unroll
        for (int nt = 0; nt < 8; ++nt) mma_u8s8(accP1[nt],  aH[1], bfr[nt][2], bfr[nt][3]);
#pragma unroll
        for (int nt = 0; nt < 8; ++nt) mma_s8s8(accP23[nt], aL[0], bfr[nt][0], bfr[nt][1]);
#pragma unroll
        for (int nt = 0; nt < 8; ++nt) mma_s8s8(accP23[nt], aL[1], bfr[nt][2], bfr[nt][3]);
        // lo limb of B: P2 (ah*bl)
#pragma unroll
        for (int nt = 0; nt < 8; ++nt)
            ldsm4(blBase + (uint32_t)(nt * 8 * BP8), bfr[nt]);
#pragma unroll
        for (int nt = 0; nt < 8; ++nt) mma_u8s8(accP23[nt], aH[0], bfr[nt][0], bfr[nt][1]);
#pragma unroll
        for (int nt = 0; nt < 8; ++nt) mma_u8s8(accP23[nt], aH[1], bfr[nt][2], bfr[nt][3]);
    }

    // epilogue: dequantize, relu, store
    const float am  = __int_as_float(g_absmaxBits);
    const float sBq = (float)Q16MAX / fmaxf(am, 1e-30f);
    const float invS = 1.f / (SA_SCALE * sBq);

    const int rowTop = m0 + w * 16 + g;
#pragma unroll
    for (int nt = 0; nt < 8; ++nt) {
        const int col = nt * 8 + t4 * 2;
        float o0 = ((float)accP1[nt][0] * 65536.f + (float)accP23[nt][0] * 256.f) * invS;
        float o1 = ((float)accP1[nt][1] * 65536.f + (float)accP23[nt][1] * 256.f) * invS;
        float o2 = ((float)accP1[nt][2] * 65536.f + (float)accP23[nt][2] * 256.f) * invS;
        float o3 = ((float)accP1[nt][3] * 65536.f + (float)accP23[nt][3] * 256.f) * invS;
        float2 v0 = make_float2(fmaxf(o0, 0.f), fmaxf(o1, 0.f));
        float2 v1 = make_float2(fmaxf(o2, 0.f), fmaxf(o3, 0.f));
        *(float2*)(out + (size_t)rowTop * DOUT + col)       = v0;
        *(float2*)(out + (size_t)(rowTop + 8) * DOUT + col) = v1;
    }
}

// ---------------------------------------------------------------------------
extern "C" void kernel_launch(void* const* d_in, const int* in_sizes, int n_in,
                              void* d_out, int out_size)
{
    const float* adj  = (const float*)d_in[0];   // [16384, 16384]
    const float* x    = (const float*)d_in[1];   // [16384, 128]
    const float* w    = (const float*)d_in[2];   // [128, 64]
    const float* bias = (const float*)d_in[3];   // [64]
    float* out = (float*)d_out;                  // [16384, 64]

    cudaFuncSetAttribute(gemm_kernel, cudaFuncAttributeMaxDynamicSharedMemorySize, SMEM_B_BYTES);

    zero_kernel<<<1, 1>>>();
    transform_kernel<<<N_ROWS / 8, 256>>>(x, w, bias);
    quantB_kernel<<<(DOUT * KDIM) / (256 * 4), 256>>>();
    gemm_kernel<<<N_ROWS / 128, 256, SMEM_B_BYTES>>>(adj, out);
}

// round 10
// speedup vs baseline: 2.0145x; 2.0145x over previous
#include <cuda_runtime.h>
#include <cuda_fp16.h>
#include <cstdint>

#define N_ROWS   16384
#define DIN      128
#define DOUT     64
#define KDIM     16384
#define MIN_NORM 1e-15f
#define ART_CLAMP (1.0f - 1e-7f)
#define MAXNORM  (1.0f - 4e-3f)

#define TK      64            // k per chunk
#define NCH     (KDIM / TK)   // 256 chunks
#define BPITCH  144           // B smem row pitch (conflict-free ldmatrix)
#define BTILE   (64 * BPITCH) // 9216 B per (hi|lo) tile
#define BSTAGES 3
#define SMEM_B_BYTES (BSTAGES * 2 * BTILE)   // 55296

#define A_SCALE 16384.0f      // 2^14, exact; A in [0, 2^-14) -> [0,1)

// Pre-split, pre-transposed tangent matrix: [DOUT][KDIM] K-major fp16 limbs
__device__ __half g_Bh[DOUT * KDIM];   // hi limb: fp16(t)
__device__ __half g_Bl[DOUT * KDIM];   // lo limb: fp16(t - hi)

// ---------------------------------------------------------------------------
// helpers
// ---------------------------------------------------------------------------
__device__ __forceinline__ uint32_t smem_u32(const void* p) {
    uint32_t a;
    asm("{ .reg .u64 t; cvta.to.shared.u64 t, %1; cvt.u32.u64 %0, t; }" : "=r"(a) : "l"(p));
    return a;
}
__device__ __forceinline__ void cp_async16(uint32_t dst, const void* src) {
    asm volatile(
        "{ .reg .u64 gp; cvta.to.global.u64 gp, %1;"
        " cp.async.cg.shared.global [%0], [gp], 16; }"
        :: "r"(dst), "l"(src) : "memory");
}
#define CP_COMMIT()  asm volatile("cp.async.commit_group;" ::: "memory")
#define CP_WAIT1()   asm volatile("cp.async.wait_group 1;" ::: "memory")
#define CP_WAIT0()   asm volatile("cp.async.wait_group 0;" ::: "memory")

__device__ __forceinline__ void ldsm4(uint32_t addr, uint32_t* r) {
    asm volatile("ldmatrix.sync.aligned.m8n8.x4.shared.b16 {%0,%1,%2,%3}, [%4];"
                 : "=r"(r[0]), "=r"(r[1]), "=r"(r[2]), "=r"(r[3]) : "r"(addr));
}
__device__ __forceinline__ void mma_f16(float* c, const uint32_t* a,
                                        uint32_t b0, uint32_t b1) {
    asm volatile(
        "mma.sync.aligned.m16n8k16.row.col.f32.f16.f16.f32 "
        "{%0,%1,%2,%3}, {%4,%5,%6,%7}, {%8,%9}, {%0,%1,%2,%3};"
        : "+f"(c[0]), "+f"(c[1]), "+f"(c[2]), "+f"(c[3])
        : "r"(a[0]), "r"(a[1]), "r"(a[2]), "r"(a[3]), "r"(b0), "r"(b1));
}
__device__ __forceinline__ float wsum(float v) {
#pragma unroll
    for (int o = 16; o > 0; o >>= 1) v += __shfl_xor_sync(0xffffffffu, v, o);
    return v;
}

// ---------------------------------------------------------------------------
// Kernel A: hyperbolic transform -> tangent -> fp16 hi/lo limbs, K-major.
// Warp-per-row; all reductions via shfl. (structure proven in R4)
// ---------------------------------------------------------------------------
__global__ __launch_bounds__(256) void transform_kernel(
    const float* __restrict__ X,
    const float* __restrict__ W,
    const float* __restrict__ bias)
{
    __shared__ float2 sW2[DIN * 32];   // [k][t] = (W[k][t], W[k][t+32])

    const int tid = threadIdx.x;
    for (int i = tid; i < DIN * 32; i += 256) {
        const int k = i >> 5, t = i & 31;
        sW2[i] = make_float2(W[k * DOUT + t], W[k * DOUT + t + 32]);
    }
    __syncthreads();

    const int w    = tid >> 5;
    const int lane = tid & 31;
    const int row  = blockIdx.x * 8 + w;

    // hyp_bias = proj(expmap0(bias))
    float b1 = bias[lane], b2v = bias[lane + 32];
    float b2 = wsum(b1 * b1 + b2v * b2v);
    float bn = fmaxf(sqrtf(b2), MIN_NORM);
    float tb = tanhf(bn) / bn;
    float e1 = tb * b1, e2v = tb * b2v;
    float e2 = wsum(e1 * e1 + e2v * e2v);
    float en = fmaxf(sqrtf(e2), MIN_NORM);
    float sc = (en > MAXNORM) ? (MAXNORM / en) : 1.f;
    float h1 = e1 * sc, h2v = e2v * sc;
    float h2 = wsum(h1 * h1 + h2v * h2v);

    float xr[4];
#pragma unroll
    for (int j = 0; j < 4; ++j) xr[j] = X[(size_t)row * DIN + lane + 32 * j];
    float x2 = wsum(xr[0] * xr[0] + xr[1] * xr[1] + xr[2] * xr[2] + xr[3] * xr[3]);

    float ma = 0.f, mb = 0.f;
#pragma unroll
    for (int j = 0; j < 4; ++j) {
#pragma unroll
        for (int l = 0; l < 32; ++l) {
            const float xv = __shfl_sync(0xffffffffu, xr[j], l);
            const float2 wv = sW2[(j * 32 + l) * 32 + lane];
            ma = fmaf(xv, wv.x, ma);
            mb = fmaf(xv, wv.y, mb);
        }
    }

    float m2 = wsum(ma * ma + mb * mb);
    float xn = fmaxf(sqrtf(x2), MIN_NORM);
    float mn = fmaxf(sqrtf(m2), MIN_NORM);

    float artx = atanhf(fminf(xn, ART_CLAMP));
    float tf   = tanhf(mn / xn * artx) / mn;
    float r1 = tf * ma, r2v = tf * mb;
    if (m2 == 0.f) { r1 = 0.f; r2v = 0.f; }

    float r2 = wsum(r1 * r1 + r2v * r2v);
    float rh = wsum(r1 * h1 + r2v * h2v);
    float al  = 1.f + 2.f * rh + h2;
    float den = fmaxf(1.f + 2.f * rh + r2 * h2, MIN_NORM);
    float p1  = (al * r1  + (1.f - r2) * h1)  / den;
    float p2v = (al * r2v + (1.f - r2) * h2v) / den;

    float p2 = wsum(p1 * p1 + p2v * p2v);
    float pn = fmaxf(sqrtf(p2), MIN_NORM);
    if (pn > MAXNORM) {
        float s = MAXNORM / pn;
        p1 *= s; p2v *= s; pn = MAXNORM;
    }

    float lf = atanhf(fminf(pn, ART_CLAMP)) / pn;
    float t1 = lf * p1, t2 = lf * p2v;

    // split to fp16 limbs (hi + lo captures 22 bits) and store K-major
    __half h1a = __float2half(t1);
    __half h2a = __float2half(t2);
    g_Bh[(size_t)lane * KDIM + row]        = h1a;
    g_Bh[(size_t)(lane + 32) * KDIM + row] = h2a;
    g_Bl[(size_t)lane * KDIM + row]        = __float2half(t1 - __half2float(h1a));
    g_Bl[(size_t)(lane + 32) * KDIM + row] = __float2half(t2 - __half2float(h2a));
}

// ---------------------------------------------------------------------------
// Kernel B: out = relu(A @ T) via fp16 mma.sync, 2 products: a*bh + a*bl.
// 128 CTAs x 256 thr; warp m16 x n64; K-chunk 64. R4 pipeline verbatim:
// A: LDG -> regs (cross-iteration prefetch) -> cvt. B: 3-stage cp.async.
// MMA schedule: ldsm-all-first, nt-major bursts, dual accumulator banks.
// ---------------------------------------------------------------------------
struct APre { float2 v[16]; };

__device__ __forceinline__ void ldA(APre& p, const float* pa0, const float* pa8, int kb) {
#pragma unroll
    for (int kf = 0; kf < 4; ++kf) {
        p.v[kf * 4 + 0] = *(const float2*)(pa0 + kb + kf * 16);
        p.v[kf * 4 + 1] = *(const float2*)(pa0 + kb + kf * 16 + 8);
        p.v[kf * 4 + 2] = *(const float2*)(pa8 + kb + kf * 16);
        p.v[kf * 4 + 3] = *(const float2*)(pa8 + kb + kf * 16 + 8);
    }
}

// mma fragment order: a0=(g,c0) a1=(g+8,c0) a2=(g,c0+8) a3=(g+8,c0+8)
__device__ __forceinline__ void cvtA(const APre& p, uint32_t* ah) {
    const int map[4] = {0, 2, 1, 3};
#pragma unroll
    for (int kf = 0; kf < 4; ++kf) {
#pragma unroll
        for (int j = 0; j < 4; ++j) {
            const float2 v = p.v[kf * 4 + map[j]];
            const __half2 h = __floats2half2_rn(v.x * A_SCALE, v.y * A_SCALE);
            ah[kf * 4 + j] = *(const uint32_t*)&h;
        }
    }
}

__global__ __launch_bounds__(256, 1) void gemm_kernel(
    const float* __restrict__ A,
    float* __restrict__ out)
{
    extern __shared__ __align__(128) char sB[];   // [stage][hi/lo][64 * BPITCH]

    const int tid  = threadIdx.x;
    const int w    = tid >> 5;
    const int lane = tid & 31;
    const int g    = lane >> 2;
    const int t4   = lane & 3;
    const int m0   = blockIdx.x * 128;

    const float* pa0 = A + (size_t)(m0 + w * 16 + g) * KDIM + 2 * t4;
    const float* pa8 = pa0 + (size_t)8 * KDIM;

    // B cp.async mapping: 4 x 16B per thread per stage
    const int n0 = tid >> 3, q0 = tid & 7;
    const int n1 = (tid + 256) >> 3, q1 = tid & 7;
    const uint32_t sb0 = smem_u32(sB);
    const uint32_t dOff0 = (uint32_t)(n0 * BPITCH + q0 * 16);
    const uint32_t dOff1 = (uint32_t)(n1 * BPITCH + q1 * 16);
    const __half* srcH0 = &g_Bh[(size_t)n0 * KDIM + q0 * 8];
    const __half* srcH1 = &g_Bh[(size_t)n1 * KDIM + q1 * 8];
    const __half* srcL0 = &g_Bl[(size_t)n0 * KDIM + q0 * 8];
    const __half* srcL1 = &g_Bl[(size_t)n1 * KDIM + q1 * 8];

    // ldmatrix lane offset
    const uint32_t lmOff = (uint32_t)((lane & 7) * BPITCH + (lane >> 3) * 16);

    float accA[8][4], accB[8][4];
#pragma unroll
    for (int i = 0; i < 8; ++i)
#pragma unroll
        for (int j = 0; j < 4; ++j) { accA[i][j] = 0.f; accB[i][j] = 0.f; }

    // prologue: B stages 0,1 ; A chunk 0
#pragma unroll
    for (int s = 0; s < 2; ++s) {
        const int kb = s * TK;
        const uint32_t db = sb0 + (uint32_t)(s * 2 * BTILE);
        cp_async16(db + dOff0,         srcH0 + kb);
        cp_async16(db + dOff1,         srcH1 + kb);
        cp_async16(db + BTILE + dOff0, srcL0 + kb);
        cp_async16(db + BTILE + dOff1, srcL1 + kb);
        CP_COMMIT();
    }

    APre pre;
    ldA(pre, pa0, pa8, 0);

    uint32_t ahF[16];
    uint32_t bf[8][4];

    for (int i = 0; i < NCH; ++i) {
        const int s = i % BSTAGES;

        if (i < NCH - 1) { CP_WAIT1(); } else { CP_WAIT0(); }
        __syncthreads();

        // issue B stage i+2 (slot consumed at chunk i-1; barrier above makes it safe)
        if (i + 2 < NCH) {
            const int kb = (i + 2) * TK;
            const uint32_t db = sb0 + (uint32_t)(((i + 2) % BSTAGES) * 2 * BTILE);
            cp_async16(db + dOff0,         srcH0 + kb);
            cp_async16(db + dOff1,         srcH1 + kb);
            cp_async16(db + BTILE + dOff0, srcL0 + kb);
            cp_async16(db + BTILE + dOff1, srcL1 + kb);
            CP_COMMIT();
        }

        // convert A chunk i (regs loaded last iter), then prefetch chunk i+1
        cvtA(pre, ahF);
        if (i + 1 < NCH) ldA(pre, pa0, pa8, (i + 1) * TK);

        const uint32_t bhBase = sb0 + (uint32_t)(s * 2 * BTILE) + lmOff;
        const uint32_t blBase = bhBase + BTILE;

#pragma unroll
        for (int p = 0; p < 2; ++p) {
            const uint32_t* ah0 = ahF + (2 * p) * 4;
            const uint32_t* ah1 = ahF + (2 * p + 1) * 4;
            const uint32_t pOff = (uint32_t)(p * 64);

            // hi tile: all ldsm first, then nt-major bursts (acc reuse distance 8)
#pragma unroll
            for (int nt = 0; nt < 8; ++nt)
                ldsm4(bhBase + (uint32_t)(nt * 8 * BPITCH) + pOff, bf[nt]);
#pragma unroll
            for (int nt = 0; nt < 8; ++nt) mma_f16(accA[nt], ah0, bf[nt][0], bf[nt][1]);
#pragma unroll
            for (int nt = 0; nt < 8; ++nt) mma_f16(accA[nt], ah1, bf[nt][2], bf[nt][3]);
            // lo tile
#pragma unroll
            for (int nt = 0; nt < 8; ++nt)
                ldsm4(blBase + (uint32_t)(nt * 8 * BPITCH) + pOff, bf[nt]);
#pragma unroll
            for (int nt = 0; nt < 8; ++nt) mma_f16(accB[nt], ah0, bf[nt][0], bf[nt][1]);
#pragma unroll
            for (int nt = 0; nt < 8; ++nt) mma_f16(accB[nt], ah1, bf[nt][2], bf[nt][3]);
        }
    }

    // epilogue: relu((accA+accB)/A_SCALE)
    const float invS = 1.f / A_SCALE;
    const int rowTop = m0 + w * 16 + g;
#pragma unroll
    for (int nt = 0; nt < 8; ++nt) {
        const int col = nt * 8 + t4 * 2;
        float2 v0 = make_float2(fmaxf((accA[nt][0] + accB[nt][0]) * invS, 0.f),
                                fmaxf((accA[nt][1] + accB[nt][1]) * invS, 0.f));
        float2 v1 = make_float2(fmaxf((accA[nt][2] + accB[nt][2]) * invS, 0.f),
                                fmaxf((accA[nt][3] + accB[nt][3]) * invS, 0.f));
        *(float2*)(out + (size_t)rowTop * DOUT + col)       = v0;
        *(float2*)(out + (size_t)(rowTop + 8) * DOUT + col) = v1;
    }
}

// ---------------------------------------------------------------------------
extern "C" void kernel_launch(void* const* d_in, const int* in_sizes, int n_in,
                              void* d_out, int out_size)
{
    const float* adj  = (const float*)d_in[0];   // [16384, 16384]
    const float* x    = (const float*)d_in[1];   // [16384, 128]
    const float* w    = (const float*)d_in[2];   // [128, 64]
    const float* bias = (const float*)d_in[3];   // [64]
    float* out = (float*)d_out;                  // [16384, 64]

    cudaFuncSetAttribute(gemm_kernel, cudaFuncAttributeMaxDynamicSharedMemorySize, SMEM_B_BYTES);

    transform_kernel<<<N_ROWS / 8, 256>>>(x, w, bias);
    gemm_kernel<<<N_ROWS / 128, 256, SMEM_B_BYTES>>>(adj, out);
}

// round 12
// speedup vs baseline: 2.3458x; 1.1644x over previous
#include <cuda_runtime.h>
#include <cuda_fp16.h>
#include <cstdint>

#define N_ROWS   16384
#define DIN      128
#define DOUT     64
#define KDIM     16384
#define MIN_NORM 1e-15f
#define ART_CLAMP (1.0f - 1e-7f)
#define MAXNORM  (1.0f - 4e-3f)

#define TK      64                  // k per chunk
#define NCH     (KDIM / TK)         // 256 chunks
#define APITCH  272                 // A smem row pitch (256B data + 16B pad -> 2-way max)
#define ATILE   (128 * APITCH)      // 34816
#define BPITCH  144                 // B smem row pitch (128B data + 16B pad, ldsm-clean)
#define BTILE   (64 * BPITCH)       // 9216
#define STAGE   (ATILE + BTILE)     // 44032
#define BSTAGES 3
#define SMEM_BYTES (BSTAGES * STAGE)   // 132096

#define A_SCALE 16384.0f            // 2^14 exact; A in [0, 2^-14) -> [0,1)

// Tangent matrix, single fp16, K-major [DOUT][KDIM]
__device__ __half g_Bf[DOUT * KDIM];

// ---------------------------------------------------------------------------
// helpers
// ---------------------------------------------------------------------------
__device__ __forceinline__ uint32_t smem_u32(const void* p) {
    uint32_t a;
    asm("{ .reg .u64 t; cvta.to.shared.u64 t, %1; cvt.u32.u64 %0, t; }" : "=r"(a) : "l"(p));
    return a;
}
__device__ __forceinline__ void cp_async16(uint32_t dst, const void* src) {
    asm volatile(
        "{ .reg .u64 gp; cvta.to.global.u64 gp, %1;"
        " cp.async.cg.shared.global [%0], [gp], 16; }"
        :: "r"(dst), "l"(src) : "memory");
}
#define CP_COMMIT()  asm volatile("cp.async.commit_group;" ::: "memory")
#define CP_WAIT1()   asm volatile("cp.async.wait_group 1;" ::: "memory")
#define CP_WAIT0()   asm volatile("cp.async.wait_group 0;" ::: "memory")

__device__ __forceinline__ void ldsm4(uint32_t addr, uint32_t* r) {
    asm volatile("ldmatrix.sync.aligned.m8n8.x4.shared.b16 {%0,%1,%2,%3}, [%4];"
                 : "=r"(r[0]), "=r"(r[1]), "=r"(r[2]), "=r"(r[3]) : "r"(addr));
}
__device__ __forceinline__ void mma_f16(float* c, const uint32_t* a,
                                        uint32_t b0, uint32_t b1) {
    asm volatile(
        "mma.sync.aligned.m16n8k16.row.col.f32.f16.f16.f32 "
        "{%0,%1,%2,%3}, {%4,%5,%6,%7}, {%8,%9}, {%0,%1,%2,%3};"
        : "+f"(c[0]), "+f"(c[1]), "+f"(c[2]), "+f"(c[3])
        : "r"(a[0]), "r"(a[1]), "r"(a[2]), "r"(a[3]), "r"(b0), "r"(b1));
}
__device__ __forceinline__ float wsum(float v) {
#pragma unroll
    for (int o = 16; o > 0; o >>= 1) v += __shfl_xor_sync(0xffffffffu, v, o);
    return v;
}
// scale by A_SCALE and split one float2 into hi/lo fp16x2 limbs (both normal-range)
__device__ __forceinline__ void split2(float2 f, uint32_t& hi, uint32_t& lo) {
    const float sx = f.x * A_SCALE;
    const float sy = f.y * A_SCALE;
    __half2 h = __floats2half2_rn(sx, sy);
    float2 r = __half22float2(h);
    __half2 l = __floats2half2_rn(sx - r.x, sy - r.y);
    hi = *(const uint32_t*)&h;
    lo = *(const uint32_t*)&l;
}

// ---------------------------------------------------------------------------
// Kernel A: hyperbolic transform -> tangent -> single fp16, K-major transposed.
// Warp-per-row; all reductions via shfl. (structure proven R4..R10)
// ---------------------------------------------------------------------------
__global__ __launch_bounds__(256) void transform_kernel(
    const float* __restrict__ X,
    const float* __restrict__ W,
    const float* __restrict__ bias)
{
    __shared__ float2 sW2[DIN * 32];   // [k][t] = (W[k][t], W[k][t+32])

    const int tid = threadIdx.x;
    for (int i = tid; i < DIN * 32; i += 256) {
        const int k = i >> 5, t = i & 31;
        sW2[i] = make_float2(W[k * DOUT + t], W[k * DOUT + t + 32]);
    }
    __syncthreads();

    const int w    = tid >> 5;
    const int lane = tid & 31;
    const int row  = blockIdx.x * 8 + w;

    // hyp_bias = proj(expmap0(bias))
    float b1 = bias[lane], b2v = bias[lane + 32];
    float b2 = wsum(b1 * b1 + b2v * b2v);
    float bn = fmaxf(sqrtf(b2), MIN_NORM);
    float tb = tanhf(bn) / bn;
    float e1 = tb * b1, e2v = tb * b2v;
    float e2 = wsum(e1 * e1 + e2v * e2v);
    float en = fmaxf(sqrtf(e2), MIN_NORM);
    float sc = (en > MAXNORM) ? (MAXNORM / en) : 1.f;
    float h1 = e1 * sc, h2v = e2v * sc;
    float h2 = wsum(h1 * h1 + h2v * h2v);

    float xr[4];
#pragma unroll
    for (int j = 0; j < 4; ++j) xr[j] = X[(size_t)row * DIN + lane + 32 * j];
    float x2 = wsum(xr[0] * xr[0] + xr[1] * xr[1] + xr[2] * xr[2] + xr[3] * xr[3]);

    float ma = 0.f, mb = 0.f;
#pragma unroll
    for (int j = 0; j < 4; ++j) {
#pragma unroll
        for (int l = 0; l < 32; ++l) {
            const float xv = __shfl_sync(0xffffffffu, xr[j], l);
            const float2 wv = sW2[(j * 32 + l) * 32 + lane];
            ma = fmaf(xv, wv.x, ma);
            mb = fmaf(xv, wv.y, mb);
        }
    }

    float m2 = wsum(ma * ma + mb * mb);
    float xn = fmaxf(sqrtf(x2), MIN_NORM);
    float mn = fmaxf(sqrtf(m2), MIN_NORM);

    float artx = atanhf(fminf(xn, ART_CLAMP));
    float tf   = tanhf(mn / xn * artx) / mn;
    float r1 = tf * ma, r2v = tf * mb;
    if (m2 == 0.f) { r1 = 0.f; r2v = 0.f; }

    float r2 = wsum(r1 * r1 + r2v * r2v);
    float rh = wsum(r1 * h1 + r2v * h2v);
    float al  = 1.f + 2.f * rh + h2;
    float den = fmaxf(1.f + 2.f * rh + r2 * h2, MIN_NORM);
    float p1  = (al * r1  + (1.f - r2) * h1)  / den;
    float p2v = (al * r2v + (1.f - r2) * h2v) / den;

    float p2 = wsum(p1 * p1 + p2v * p2v);
    float pn = fmaxf(sqrtf(p2), MIN_NORM);
    if (pn > MAXNORM) {
        float s = MAXNORM / pn;
        p1 *= s; p2v *= s; pn = MAXNORM;
    }

    float lf = atanhf(fminf(pn, ART_CLAMP)) / pn;
    g_Bf[(size_t)lane * KDIM + row]        = __float2half(lf * p1);
    g_Bf[(size_t)(lane + 32) * KDIM + row] = __float2half(lf * p2v);
}

// ---------------------------------------------------------------------------
// Kernel B: out = relu(A @ T) via fp16 mma.sync, A split hi/lo (near-exact),
// B single fp16. 128 CTAs x 256 thr; warp m16 x n64; K-chunk 64.
// A AND B staged via 3-stage cp.async (A fp32 -> smem -> LDS -> scale+split).
// MMA schedule: ldsm-all-first, nt-major bursts, dual accumulator banks.
// ---------------------------------------------------------------------------
__global__ __launch_bounds__(256, 1) void gemm_kernel(
    const float* __restrict__ A,
    float* __restrict__ out)
{
    extern __shared__ __align__(128) char sm[];   // [stage][A(34816) | B(9216)]

    const int tid  = threadIdx.x;
    const int w    = tid >> 5;
    const int lane = tid & 31;
    const int g    = lane >> 2;
    const int t4   = lane & 3;
    const int m0   = blockIdx.x * 128;

    const uint32_t sb0 = smem_u32(sm);

    // cp.async mappings (fully coalesced)
    const int rA0 = tid >> 4, kcA = tid & 15;    // A: row rA0+16j, 16B chunk kcA
    const int rB0 = tid >> 3, kcB = tid & 7;     // B: row rB0+32j, 16B chunk kcB
    const float*  srcA0 = A + (size_t)(m0 + rA0) * KDIM + kcA * 4;
    const __half* srcB0 = g_Bf + (size_t)rB0 * KDIM + kcB * 8;
    const uint32_t dstA0 = (uint32_t)(rA0 * APITCH + kcA * 16);
    const uint32_t dstB0 = (uint32_t)(ATILE + rB0 * BPITCH + kcB * 16);

    // A LDS offsets (byte): rows w*16+g (+8), col bytes 8*t4 (+64*kf, +32)
    const uint32_t aRow0 = (uint32_t)((w * 16 + g) * APITCH + 8 * t4);
    const uint32_t aRow1 = aRow0 + 8 * APITCH;

    // ldmatrix lane offset within B tile
    const uint32_t lmOff = (uint32_t)(ATILE + (lane & 7) * BPITCH + (lane >> 3) * 16);

    float accA[8][4], accB[8][4];
#pragma unroll
    for (int i = 0; i < 8; ++i)
#pragma unroll
        for (int j = 0; j < 4; ++j) { accA[i][j] = 0.f; accB[i][j] = 0.f; }

    // prologue: stages 0,1
#pragma unroll
    for (int s = 0; s < 2; ++s) {
        const int kb = s * TK;
        const uint32_t db = sb0 + (uint32_t)(s * STAGE);
#pragma unroll
        for (int j = 0; j < 8; ++j)
            cp_async16(db + dstA0 + (uint32_t)(j * 16 * APITCH),
                       srcA0 + (size_t)j * 16 * KDIM + kb);
#pragma unroll
        for (int j = 0; j < 2; ++j)
            cp_async16(db + dstB0 + (uint32_t)(j * 32 * BPITCH),
                       srcB0 + (size_t)j * 32 * KDIM + kb);
        CP_COMMIT();
    }

    uint32_t ahF[16], alF[16];
    uint32_t bf[8][4];

    for (int i = 0; i < NCH; ++i) {
        const int s = i % BSTAGES;

        if (i < NCH - 1) { CP_WAIT1(); } else { CP_WAIT0(); }
        __syncthreads();

        // issue stage i+2 (slot consumed at chunk i-1; barrier above makes it safe)
        if (i + 2 < NCH) {
            const int kb = (i + 2) * TK;
            const uint32_t db = sb0 + (uint32_t)(((i + 2) % BSTAGES) * STAGE);
#pragma unroll
            for (int j = 0; j < 8; ++j)
                cp_async16(db + dstA0 + (uint32_t)(j * 16 * APITCH),
                           srcA0 + (size_t)j * 16 * KDIM + kb);
#pragma unroll
            for (int j = 0; j < 2; ++j)
                cp_async16(db + dstB0 + (uint32_t)(j * 32 * BPITCH),
                           srcB0 + (size_t)j * 32 * KDIM + kb);
            CP_COMMIT();
        }

        // build A fragments from smem: LDS float2 -> scale + split to fp16 limbs
        const char* stg = sm + (size_t)s * STAGE;
#pragma unroll
        for (int kf = 0; kf < 4; ++kf) {
            const uint32_t c = (uint32_t)(kf * 64);
            float2 f0 = *(const float2*)(stg + aRow0 + c);
            float2 f1 = *(const float2*)(stg + aRow1 + c);
            float2 f2 = *(const float2*)(stg + aRow0 + c + 32);
            float2 f3 = *(const float2*)(stg + aRow1 + c + 32);
            split2(f0, ahF[kf * 4 + 0], alF[kf * 4 + 0]);   // a0 = (g,   k)
            split2(f1, ahF[kf * 4 + 1], alF[kf * 4 + 1]);   // a1 = (g+8, k)
            split2(f2, ahF[kf * 4 + 2], alF[kf * 4 + 2]);   // a2 = (g,   k+8)
            split2(f3, ahF[kf * 4 + 3], alF[kf * 4 + 3]);   // a3 = (g+8, k+8)
        }

        const uint32_t bBase = sb0 + (uint32_t)(s * STAGE) + lmOff;

#pragma unroll
        for (int p = 0; p < 2; ++p) {
            const uint32_t* ah0 = ahF + (2 * p) * 4;
            const uint32_t* ah1 = ahF + (2 * p + 1) * 4;
            const uint32_t* al0 = alF + (2 * p) * 4;
            const uint32_t* al1 = alF + (2 * p + 1) * 4;
            const uint32_t pOff = (uint32_t)(p * 64);

            // all ldsm first, then nt-major bursts (acc reuse distance 8)
#pragma unroll
            for (int nt = 0; nt < 8; ++nt)
                ldsm4(bBase + (uint32_t)(nt * 8 * BPITCH) + pOff, bf[nt]);
#pragma unroll
            for (int nt = 0; nt < 8; ++nt) mma_f16(accA[nt], ah0, bf[nt][0], bf[nt][1]);
#pragma unroll
            for (int nt = 0; nt < 8; ++nt) mma_f16(accB[nt], al0, bf[nt][0], bf[nt][1]);
#pragma unroll
            for (int nt = 0; nt < 8; ++nt) mma_f16(accA[nt], ah1, bf[nt][2], bf[nt][3]);
#pragma unroll
            for (int nt = 0; nt < 8; ++nt) mma_f16(accB[nt], al1, bf[nt][2], bf[nt][3]);
        }
    }

    // epilogue: relu((accA+accB)/A_SCALE)
    const float invS = 1.f / A_SCALE;
    const int rowTop = m0 + w * 16 + g;
#pragma unroll
    for (int nt = 0; nt < 8; ++nt) {
        const int col = nt * 8 + t4 * 2;
        float2 v0 = make_float2(fmaxf((accA[nt][0] + accB[nt][0]) * invS, 0.f),
                                fmaxf((accA[nt][1] + accB[nt][1]) * invS, 0.f));
        float2 v1 = make_float2(fmaxf((accA[nt][2] + accB[nt][2]) * invS, 0.f),
                                fmaxf((accA[nt][3] + accB[nt][3]) * invS, 0.f));
        *(float2*)(out + (size_t)rowTop * DOUT + col)       = v0;
        *(float2*)(out + (size_t)(rowTop + 8) * DOUT + col) = v1;
    }
}

// ---------------------------------------------------------------------------
extern "C" void kernel_launch(void* const* d_in, const int* in_sizes, int n_in,
                              void* d_out, int out_size)
{
    const float* adj  = (const float*)d_in[0];   // [16384, 16384]
    const float* x    = (const float*)d_in[1];   // [16384, 128]
    const float* w    = (const float*)d_in[2];   // [128, 64]
    const float* bias = (const float*)d_in[3];   // [64]
    float* out = (float*)d_out;                  // [16384, 64]

    cudaFuncSetAttribute(gemm_kernel, cudaFuncAttributeMaxDynamicSharedMemorySize, SMEM_BYTES);

    transform_kernel<<<N_ROWS / 8, 256>>>(x, w, bias);
    gemm_kernel<<<N_ROWS / 128, 256, SMEM_BYTES>>>(adj, out);
}

// round 13
// speedup vs baseline: 2.6838x; 1.1441x over previous
#include <cuda_runtime.h>
#include <cuda_fp16.h>
#include <cstdint>

#define N_ROWS   16384
#define DIN      128
#define DOUT     64
#define KDIM     16384
#define MIN_NORM 1e-15f
#define ART_CLAMP (1.0f - 1e-7f)
#define MAXNORM  (1.0f - 4e-3f)

#define TK      64                  // k per chunk
#define NCH     (KDIM / TK)         // 256 chunks
#define APITCH  272                 // A smem row pitch (256B data + 16B pad -> 2-way max)
#define ATILE   (128 * APITCH)      // 34816
#define BPITCH  144                 // B smem row pitch (128B data + 16B pad, ldsm-clean)
#define BTILE   (64 * BPITCH)       // 9216
#define STAGE   (ATILE + BTILE)     // 44032
#define BSTAGES 3
#define SMEM_BYTES (BSTAGES * STAGE)   // 132096

#define A_SCALE 16384.0f            // 2^14 exact; A in [0, 2^-14) -> [0,1)

// Tangent matrix, single fp16, K-major [DOUT][KDIM]
__device__ __half g_Bf[DOUT * KDIM];

// ---------------------------------------------------------------------------
// helpers
// ---------------------------------------------------------------------------
__device__ __forceinline__ uint32_t smem_u32(const void* p) {
    uint32_t a;
    asm("{ .reg .u64 t; cvta.to.shared.u64 t, %1; cvt.u32.u64 %0, t; }" : "=r"(a) : "l"(p));
    return a;
}
__device__ __forceinline__ void cp_async16(uint32_t dst, const void* src) {
    asm volatile(
        "{ .reg .u64 gp; cvta.to.global.u64 gp, %1;"
        " cp.async.cg.shared.global [%0], [gp], 16; }"
        :: "r"(dst), "l"(src) : "memory");
}
#define CP_COMMIT()  asm volatile("cp.async.commit_group;" ::: "memory")
#define CP_WAIT1()   asm volatile("cp.async.wait_group 1;" ::: "memory")
#define CP_WAIT0()   asm volatile("cp.async.wait_group 0;" ::: "memory")

__device__ __forceinline__ void ldsm4(uint32_t addr, uint32_t* r) {
    asm volatile("ldmatrix.sync.aligned.m8n8.x4.shared.b16 {%0,%1,%2,%3}, [%4];"
                 : "=r"(r[0]), "=r"(r[1]), "=r"(r[2]), "=r"(r[3]) : "r"(addr));
}
__device__ __forceinline__ void mma_f16(float* c, const uint32_t* a,
                                        uint32_t b0, uint32_t b1) {
    asm volatile(
        "mma.sync.aligned.m16n8k16.row.col.f32.f16.f16.f32 "
        "{%0,%1,%2,%3}, {%4,%5,%6,%7}, {%8,%9}, {%0,%1,%2,%3};"
        : "+f"(c[0]), "+f"(c[1]), "+f"(c[2]), "+f"(c[3])
        : "r"(a[0]), "r"(a[1]), "r"(a[2]), "r"(a[3]), "r"(b0), "r"(b1));
}
__device__ __forceinline__ float wsum(float v) {
#pragma unroll
    for (int o = 16; o > 0; o >>= 1) v += __shfl_xor_sync(0xffffffffu, v, o);
    return v;
}
// scale by A_SCALE and convert one float2 -> fp16x2 (normal range)
__device__ __forceinline__ uint32_t cvt2(float2 f) {
    __half2 h = __floats2half2_rn(f.x * A_SCALE, f.y * A_SCALE);
    return *(const uint32_t*)&h;
}

// ---------------------------------------------------------------------------
// Kernel A: hyperbolic transform -> tangent -> single fp16, K-major transposed.
// Warp-per-row; all reductions via shfl. (unchanged, proven)
// ---------------------------------------------------------------------------
__global__ __launch_bounds__(256) void transform_kernel(
    const float* __restrict__ X,
    const float* __restrict__ W,
    const float* __restrict__ bias)
{
    __shared__ float2 sW2[DIN * 32];   // [k][t] = (W[k][t], W[k][t+32])

    const int tid = threadIdx.x;
    for (int i = tid; i < DIN * 32; i += 256) {
        const int k = i >> 5, t = i & 31;
        sW2[i] = make_float2(W[k * DOUT + t], W[k * DOUT + t + 32]);
    }
    __syncthreads();

    const int w    = tid >> 5;
    const int lane = tid & 31;
    const int row  = blockIdx.x * 8 + w;

    // hyp_bias = proj(expmap0(bias))
    float b1 = bias[lane], b2v = bias[lane + 32];
    float b2 = wsum(b1 * b1 + b2v * b2v);
    float bn = fmaxf(sqrtf(b2), MIN_NORM);
    float tb = tanhf(bn) / bn;
    float e1 = tb * b1, e2v = tb * b2v;
    float e2 = wsum(e1 * e1 + e2v * e2v);
    float en = fmaxf(sqrtf(e2), MIN_NORM);
    float sc = (en > MAXNORM) ? (MAXNORM / en) : 1.f;
    float h1 = e1 * sc, h2v = e2v * sc;
    float h2 = wsum(h1 * h1 + h2v * h2v);

    float xr[4];
#pragma unroll
    for (int j = 0; j < 4; ++j) xr[j] = X[(size_t)row * DIN + lane + 32 * j];
    float x2 = wsum(xr[0] * xr[0] + xr[1] * xr[1] + xr[2] * xr[2] + xr[3] * xr[3]);

    float ma = 0.f, mb = 0.f;
#pragma unroll
    for (int j = 0; j < 4; ++j) {
#pragma unroll
        for (int l = 0; l < 32; ++l) {
            const float xv = __shfl_sync(0xffffffffu, xr[j], l);
            const float2 wv = sW2[(j * 32 + l) * 32 + lane];
            ma = fmaf(xv, wv.x, ma);
            mb = fmaf(xv, wv.y, mb);
        }
    }

    float m2 = wsum(ma * ma + mb * mb);
    float xn = fmaxf(sqrtf(x2), MIN_NORM);
    float mn = fmaxf(sqrtf(m2), MIN_NORM);

    float artx = atanhf(fminf(xn, ART_CLAMP));
    float tf   = tanhf(mn / xn * artx) / mn;
    float r1 = tf * ma, r2v = tf * mb;
    if (m2 == 0.f) { r1 = 0.f; r2v = 0.f; }

    float r2 = wsum(r1 * r1 + r2v * r2v);
    float rh = wsum(r1 * h1 + r2v * h2v);
    float al  = 1.f + 2.f * rh + h2;
    float den = fmaxf(1.f + 2.f * rh + r2 * h2, MIN_NORM);
    float p1  = (al * r1  + (1.f - r2) * h1)  / den;
    float p2v = (al * r2v + (1.f - r2) * h2v) / den;

    float p2 = wsum(p1 * p1 + p2v * p2v);
    float pn = fmaxf(sqrtf(p2), MIN_NORM);
    if (pn > MAXNORM) {
        float s = MAXNORM / pn;
        p1 *= s; p2v *= s; pn = MAXNORM;
    }

    float lf = atanhf(fminf(pn, ART_CLAMP)) / pn;
    g_Bf[(size_t)lane * KDIM + row]        = __float2half(lf * p1);
    g_Bf[(size_t)(lane + 32) * KDIM + row] = __float2half(lf * p2v);
}

// ---------------------------------------------------------------------------
// Kernel B: out = relu(A @ T) via fp16 mma.sync, both operands single fp16
// (A scaled by 2^14; zero-mean RN errors combine to ~2.6e-4 rel).
// 128 CTAs x 256 thr; warp m16 x n64; K-chunk 64; 32 MMAs/chunk/warp.
// A AND B staged via 3-stage cp.async (A fp32 -> smem -> LDS -> scale+cvt).
// ---------------------------------------------------------------------------
__global__ __launch_bounds__(256, 1) void gemm_kernel(
    const float* __restrict__ A,
    float* __restrict__ out)
{
    extern __shared__ __align__(128) char sm[];   // [stage][A(34816) | B(9216)]

    const int tid  = threadIdx.x;
    const int w    = tid >> 5;
    const int lane = tid & 31;
    const int g    = lane >> 2;
    const int t4   = lane & 3;
    const int m0   = blockIdx.x * 128;

    const uint32_t sb0 = smem_u32(sm);

    // cp.async mappings (fully coalesced)
    const int rA0 = tid >> 4, kcA = tid & 15;    // A: row rA0+16j, 16B chunk kcA
    const int rB0 = tid >> 3, kcB = tid & 7;     // B: row rB0+32j, 16B chunk kcB
    const float*  srcA0 = A + (size_t)(m0 + rA0) * KDIM + kcA * 4;
    const __half* srcB0 = g_Bf + (size_t)rB0 * KDIM + kcB * 8;
    const uint32_t dstA0 = (uint32_t)(rA0 * APITCH + kcA * 16);
    const uint32_t dstB0 = (uint32_t)(ATILE + rB0 * BPITCH + kcB * 16);

    // A LDS offsets (byte): rows w*16+g (+8), col bytes 8*t4 (+64*kf, +32)
    const uint32_t aRow0 = (uint32_t)((w * 16 + g) * APITCH + 8 * t4);
    const uint32_t aRow1 = aRow0 + 8 * APITCH;

    // ldmatrix lane offset within B tile
    const uint32_t lmOff = (uint32_t)(ATILE + (lane & 7) * BPITCH + (lane >> 3) * 16);

    float acc[8][4];
#pragma unroll
    for (int i = 0; i < 8; ++i)
#pragma unroll
        for (int j = 0; j < 4; ++j) acc[i][j] = 0.f;

    // prologue: stages 0,1
#pragma unroll
    for (int s = 0; s < 2; ++s) {
        const int kb = s * TK;
        const uint32_t db = sb0 + (uint32_t)(s * STAGE);
#pragma unroll
        for (int j = 0; j < 8; ++j)
            cp_async16(db + dstA0 + (uint32_t)(j * 16 * APITCH),
                       srcA0 + (size_t)j * 16 * KDIM + kb);
#pragma unroll
        for (int j = 0; j < 2; ++j)
            cp_async16(db + dstB0 + (uint32_t)(j * 32 * BPITCH),
                       srcB0 + (size_t)j * 32 * KDIM + kb);
        CP_COMMIT();
    }

    uint32_t ahF[16];
    uint32_t bf[8][4];

    for (int i = 0; i < NCH; ++i) {
        const int s = i % BSTAGES;

        if (i < NCH - 1) { CP_WAIT1(); } else { CP_WAIT0(); }
        __syncthreads();

        // issue stage i+2 (slot consumed at chunk i-1; barrier above makes it safe)
        if (i + 2 < NCH) {
            const int kb = (i + 2) * TK;
            const uint32_t db = sb0 + (uint32_t)(((i + 2) % BSTAGES) * STAGE);
#pragma unroll
            for (int j = 0; j < 8; ++j)
                cp_async16(db + dstA0 + (uint32_t)(j * 16 * APITCH),
                           srcA0 + (size_t)j * 16 * KDIM + kb);
#pragma unroll
            for (int j = 0; j < 2; ++j)
                cp_async16(db + dstB0 + (uint32_t)(j * 32 * BPITCH),
                           srcB0 + (size_t)j * 32 * KDIM + kb);
            CP_COMMIT();
        }

        // build A fragments from smem: LDS float2 -> scale + cvt to fp16x2
        const char* stg = sm + (size_t)s * STAGE;
#pragma unroll
        for (int kf = 0; kf < 4; ++kf) {
            const uint32_t c = (uint32_t)(kf * 64);
            ahF[kf * 4 + 0] = cvt2(*(const float2*)(stg + aRow0 + c));        // (g,   k)
            ahF[kf * 4 + 1] = cvt2(*(const float2*)(stg + aRow1 + c));        // (g+8, k)
            ahF[kf * 4 + 2] = cvt2(*(const float2*)(stg + aRow0 + c + 32));   // (g,   k+8)
            ahF[kf * 4 + 3] = cvt2(*(const float2*)(stg + aRow1 + c + 32));   // (g+8, k+8)
        }

        const uint32_t bBase = sb0 + (uint32_t)(s * STAGE) + lmOff;

#pragma unroll
        for (int p = 0; p < 2; ++p) {
            const uint32_t* ah0 = ahF + (2 * p) * 4;
            const uint32_t* ah1 = ahF + (2 * p + 1) * 4;
            const uint32_t pOff = (uint32_t)(p * 64);

            // all ldsm first, then nt-major bursts (acc reuse distance 8)
#pragma unroll
            for (int nt = 0; nt < 8; ++nt)
                ldsm4(bBase + (uint32_t)(nt * 8 * BPITCH) + pOff, bf[nt]);
#pragma unroll
            for (int nt = 0; nt < 8; ++nt) mma_f16(acc[nt], ah0, bf[nt][0], bf[nt][1]);
#pragma unroll
            for (int nt = 0; nt < 8; ++nt) mma_f16(acc[nt], ah1, bf[nt][2], bf[nt][3]);
        }
    }

    // epilogue: relu(acc/A_SCALE)
    const float invS = 1.f / A_SCALE;
    const int rowTop = m0 + w * 16 + g;
#pragma unroll
    for (int nt = 0; nt < 8; ++nt) {
        const int col = nt * 8 + t4 * 2;
        float2 v0 = make_float2(fmaxf(acc[nt][0] * invS, 0.f),
                                fmaxf(acc[nt][1] * invS, 0.f));
        float2 v1 = make_float2(fmaxf(acc[nt][2] * invS, 0.f),
                                fmaxf(acc[nt][3] * invS, 0.f));
        *(float2*)(out + (size_t)rowTop * DOUT + col)       = v0;
        *(float2*)(out + (size_t)(rowTop + 8) * DOUT + col) = v1;
    }
}

// ---------------------------------------------------------------------------
extern "C" void kernel_launch(void* const* d_in, const int* in_sizes, int n_in,
                              void* d_out, int out_size)
{
    const float* adj  = (const float*)d_in[0];   // [16384, 16384]
    const float* x    = (const float*)d_in[1];   // [16384, 128]
    const float* w    = (const float*)d_in[2];   // [128, 64]
    const float* bias = (const float*)d_in[3];   // [64]
    float* out = (float*)d_out;                  // [16384, 64]

    cudaFuncSetAttribute(gemm_kernel, cudaFuncAttributeMaxDynamicSharedMemorySize, SMEM_BYTES);

    transform_kernel<<<N_ROWS / 8, 256>>>(x, w, bias);
    gemm_kernel<<<N_ROWS / 128, 256, SMEM_BYTES>>>(adj, out);
}

// round 14
// speedup vs baseline: 2.6874x; 1.0014x over previous
#include <cuda_runtime.h>
#include <cuda_fp16.h>
#include <cstdint>

#define N_ROWS   16384
#define DIN      128
#define DOUT     64
#define KDIM     16384
#define MIN_NORM 1e-15f
#define ART_CLAMP (1.0f - 1e-7f)
#define MAXNORM  (1.0f - 4e-3f)

#define TK      64                  // k per chunk
#define NCH     (KDIM / TK)         // 256 chunks
#define APITCH  272                 // A smem row pitch (256B data + 16B pad -> 2-way max)
#define ATILE   (128 * APITCH)      // 34816
#define BPITCH  144                 // B smem row pitch (128B data + 16B pad, ldsm-clean)
#define BTILE   (64 * BPITCH)       // 9216
#define STAGE   (ATILE + BTILE)     // 44032
#define BSTAGES 3
#define SMEM_BYTES (BSTAGES * STAGE)   // 132096

#define A_SCALE 16384.0f            // 2^14 exact; A in [0, 2^-14) -> [0,1)

// Tangent matrix, single fp16, K-major [DOUT][KDIM]
__device__ __half g_Bf[DOUT * KDIM];

// ---------------------------------------------------------------------------
// helpers
// ---------------------------------------------------------------------------
__device__ __forceinline__ uint32_t smem_u32(const void* p) {
    uint32_t a;
    asm("{ .reg .u64 t; cvta.to.shared.u64 t, %1; cvt.u32.u64 %0, t; }" : "=r"(a) : "l"(p));
    return a;
}
__device__ __forceinline__ void cp_async16(uint32_t dst, const void* src) {
    asm volatile(
        "{ .reg .u64 gp; cvta.to.global.u64 gp, %1;"
        " cp.async.cg.shared.global [%0], [gp], 16; }"
        :: "r"(dst), "l"(src) : "memory");
}
#define CP_COMMIT()  asm volatile("cp.async.commit_group;" ::: "memory")
#define CP_WAIT1()   asm volatile("cp.async.wait_group 1;" ::: "memory")
#define CP_WAIT0()   asm volatile("cp.async.wait_group 0;" ::: "memory")

__device__ __forceinline__ void ldsm4(uint32_t addr, uint32_t* r) {
    asm volatile("ldmatrix.sync.aligned.m8n8.x4.shared.b16 {%0,%1,%2,%3}, [%4];"
                 : "=r"(r[0]), "=r"(r[1]), "=r"(r[2]), "=r"(r[3]) : "r"(addr));
}
__device__ __forceinline__ void mma_f16(float* c, const uint32_t* a,
                                        uint32_t b0, uint32_t b1) {
    asm volatile(
        "mma.sync.aligned.m16n8k16.row.col.f32.f16.f16.f32 "
        "{%0,%1,%2,%3}, {%4,%5,%6,%7}, {%8,%9}, {%0,%1,%2,%3};"
        : "+f"(c[0]), "+f"(c[1]), "+f"(c[2]), "+f"(c[3])
        : "r"(a[0]), "r"(a[1]), "r"(a[2]), "r"(a[3]), "r"(b0), "r"(b1));
}
__device__ __forceinline__ float wsum(float v) {
#pragma unroll
    for (int o = 16; o > 0; o >>= 1) v += __shfl_xor_sync(0xffffffffu, v, o);
    return v;
}
// scale by A_SCALE and convert one float2 -> fp16x2 (normal range)
__device__ __forceinline__ uint32_t cvt2(float2 f) {
    __half2 h = __floats2half2_rn(f.x * A_SCALE, f.y * A_SCALE);
    return *(const uint32_t*)&h;
}

// ---------------------------------------------------------------------------
// Kernel A: hyperbolic transform -> tangent -> single fp16, K-major transposed.
// Warp-per-row; all reductions via shfl. (unchanged, proven)
// ---------------------------------------------------------------------------
__global__ __launch_bounds__(256) void transform_kernel(
    const float* __restrict__ X,
    const float* __restrict__ W,
    const float* __restrict__ bias)
{
    __shared__ float2 sW2[DIN * 32];   // [k][t] = (W[k][t], W[k][t+32])

    const int tid = threadIdx.x;
    for (int i = tid; i < DIN * 32; i += 256) {
        const int k = i >> 5, t = i & 31;
        sW2[i] = make_float2(W[k * DOUT + t], W[k * DOUT + t + 32]);
    }
    __syncthreads();

    const int w    = tid >> 5;
    const int lane = tid & 31;
    const int row  = blockIdx.x * 8 + w;

    // hyp_bias = proj(expmap0(bias))
    float b1 = bias[lane], b2v = bias[lane + 32];
    float b2 = wsum(b1 * b1 + b2v * b2v);
    float bn = fmaxf(sqrtf(b2), MIN_NORM);
    float tb = tanhf(bn) / bn;
    float e1 = tb * b1, e2v = tb * b2v;
    float e2 = wsum(e1 * e1 + e2v * e2v);
    float en = fmaxf(sqrtf(e2), MIN_NORM);
    float sc = (en > MAXNORM) ? (MAXNORM / en) : 1.f;
    float h1 = e1 * sc, h2v = e2v * sc;
    float h2 = wsum(h1 * h1 + h2v * h2v);

    float xr[4];
#pragma unroll
    for (int j = 0; j < 4; ++j) xr[j] = X[(size_t)row * DIN + lane + 32 * j];
    float x2 = wsum(xr[0] * xr[0] + xr[1] * xr[1] + xr[2] * xr[2] + xr[3] * xr[3]);

    float ma = 0.f, mb = 0.f;
#pragma unroll
    for (int j = 0; j < 4; ++j) {
#pragma unroll
        for (int l = 0; l < 32; ++l) {
            const float xv = __shfl_sync(0xffffffffu, xr[j], l);
            const float2 wv = sW2[(j * 32 + l) * 32 + lane];
            ma = fmaf(xv, wv.x, ma);
            mb = fmaf(xv, wv.y, mb);
        }
    }

    float m2 = wsum(ma * ma + mb * mb);
    float xn = fmaxf(sqrtf(x2), MIN_NORM);
    float mn = fmaxf(sqrtf(m2), MIN_NORM);

    float artx = atanhf(fminf(xn, ART_CLAMP));
    float tf   = tanhf(mn / xn * artx) / mn;
    float r1 = tf * ma, r2v = tf * mb;
    if (m2 == 0.f) { r1 = 0.f; r2v = 0.f; }

    float r2 = wsum(r1 * r1 + r2v * r2v);
    float rh = wsum(r1 * h1 + r2v * h2v);
    float al  = 1.f + 2.f * rh + h2;
    float den = fmaxf(1.f + 2.f * rh + r2 * h2, MIN_NORM);
    float p1  = (al * r1  + (1.f - r2) * h1)  / den;
    float p2v = (al * r2v + (1.f - r2) * h2v) / den;

    float p2 = wsum(p1 * p1 + p2v * p2v);
    float pn = fmaxf(sqrtf(p2), MIN_NORM);
    if (pn > MAXNORM) {
        float s = MAXNORM / pn;
        p1 *= s; p2v *= s; pn = MAXNORM;
    }

    float lf = atanhf(fminf(pn, ART_CLAMP)) / pn;
    g_Bf[(size_t)lane * KDIM + row]        = __float2half(lf * p1);
    g_Bf[(size_t)(lane + 32) * KDIM + row] = __float2half(lf * p2v);
}

// ---------------------------------------------------------------------------
// Kernel B: out = relu(A @ T) via fp16 mma.sync, both operands single fp16
// (A scaled by 2^14; zero-mean RN errors combine to ~2.6e-4 rel).
// 128 CTAs x 256 thr; warp m16 x n64; K-chunk 64; 32 MMAs/chunk/warp.
// A AND B staged via 3-stage cp.async (A fp32 -> smem -> LDS -> scale+cvt).
// ---------------------------------------------------------------------------
__global__ __launch_bounds__(256, 1) void gemm_kernel(
    const float* __restrict__ A,
    float* __restrict__ out)
{
    extern __shared__ __align__(128) char sm[];   // [stage][A(34816) | B(9216)]

    const int tid  = threadIdx.x;
    const int w    = tid >> 5;
    const int lane = tid & 31;
    const int g    = lane >> 2;
    const int t4   = lane & 3;
    const int m0   = blockIdx.x * 128;

    const uint32_t sb0 = smem_u32(sm);

    // cp.async mappings (fully coalesced)
    const int rA0 = tid >> 4, kcA = tid & 15;    // A: row rA0+16j, 16B chunk kcA
    const int rB0 = tid >> 3, kcB = tid & 7;     // B: row rB0+32j, 16B chunk kcB
    const float*  srcA0 = A + (size_t)(m0 + rA0) * KDIM + kcA * 4;
    const __half* srcB0 = g_Bf + (size_t)rB0 * KDIM + kcB * 8;
    const uint32_t dstA0 = (uint32_t)(rA0 * APITCH + kcA * 16);
    const uint32_t dstB0 = (uint32_t)(ATILE + rB0 * BPITCH + kcB * 16);

    // A LDS offsets (byte): rows w*16+g (+8), col bytes 8*t4 (+64*kf, +32)
    const uint32_t aRow0 = (uint32_t)((w * 16 + g) * APITCH + 8 * t4);
    const uint32_t aRow1 = aRow0 + 8 * APITCH;

    // ldmatrix lane offset within B tile
    const uint32_t lmOff = (uint32_t)(ATILE + (lane & 7) * BPITCH + (lane >> 3) * 16);

    float acc[8][4];
#pragma unroll
    for (int i = 0; i < 8; ++i)
#pragma unroll
        for (int j = 0; j < 4; ++j) acc[i][j] = 0.f;

    // prologue: stages 0,1
#pragma unroll
    for (int s = 0; s < 2; ++s) {
        const int kb = s * TK;
        const uint32_t db = sb0 + (uint32_t)(s * STAGE);
#pragma unroll
        for (int j = 0; j < 8; ++j)
            cp_async16(db + dstA0 + (uint32_t)(j * 16 * APITCH),
                       srcA0 + (size_t)j * 16 * KDIM + kb);
#pragma unroll
        for (int j = 0; j < 2; ++j)
            cp_async16(db + dstB0 + (uint32_t)(j * 32 * BPITCH),
                       srcB0 + (size_t)j * 32 * KDIM + kb);
        CP_COMMIT();
    }

    uint32_t ahF[16];
    uint32_t bf[8][4];

    for (int i = 0; i < NCH; ++i) {
        const int s = i % BSTAGES;

        if (i < NCH - 1) { CP_WAIT1(); } else { CP_WAIT0(); }
        __syncthreads();

        // issue stage i+2 (slot consumed at chunk i-1; barrier above makes it safe)
        if (i + 2 < NCH) {
            const int kb = (i + 2) * TK;
            const uint32_t db = sb0 + (uint32_t)(((i + 2) % BSTAGES) * STAGE);
#pragma unroll
            for (int j = 0; j < 8; ++j)
                cp_async16(db + dstA0 + (uint32_t)(j * 16 * APITCH),
                           srcA0 + (size_t)j * 16 * KDIM + kb);
#pragma unroll
            for (int j = 0; j < 2; ++j)
                cp_async16(db + dstB0 + (uint32_t)(j * 32 * BPITCH),
                           srcB0 + (size_t)j * 32 * KDIM + kb);
            CP_COMMIT();
        }

        // build A fragments from smem: LDS float2 -> scale + cvt to fp16x2
        const char* stg = sm + (size_t)s * STAGE;
#pragma unroll
        for (int kf = 0; kf < 4; ++kf) {
            const uint32_t c = (uint32_t)(kf * 64);
            ahF[kf * 4 + 0] = cvt2(*(const float2*)(stg + aRow0 + c));        // (g,   k)
            ahF[kf * 4 + 1] = cvt2(*(const float2*)(stg + aRow1 + c));        // (g+8, k)
            ahF[kf * 4 + 2] = cvt2(*(const float2*)(stg + aRow0 + c + 32));   // (g,   k+8)
            ahF[kf * 4 + 3] = cvt2(*(const float2*)(stg + aRow1 + c + 32));   // (g+8, k+8)
        }

        const uint32_t bBase = sb0 + (uint32_t)(s * STAGE) + lmOff;

#pragma unroll
        for (int p = 0; p < 2; ++p) {
            const uint32_t* ah0 = ahF + (2 * p) * 4;
            const uint32_t* ah1 = ahF + (2 * p + 1) * 4;
            const uint32_t pOff = (uint32_t)(p * 64);

            // all ldsm first, then nt-major bursts (acc reuse distance 8)
#pragma unroll
            for (int nt = 0; nt < 8; ++nt)
                ldsm4(bBase + (uint32_t)(nt * 8 * BPITCH) + pOff, bf[nt]);
#pragma unroll
            for (int nt = 0; nt < 8; ++nt) mma_f16(acc[nt], ah0, bf[nt][0], bf[nt][1]);
#pragma unroll
            for (int nt = 0; nt < 8; ++nt) mma_f16(acc[nt], ah1, bf[nt][2], bf[nt][3]);
        }
    }

    // epilogue: relu(acc/A_SCALE)
    const float invS = 1.f / A_SCALE;
    const int rowTop = m0 + w * 16 + g;
#pragma unroll
    for (int nt = 0; nt < 8; ++nt) {
        const int col = nt * 8 + t4 * 2;
        float2 v0 = make_float2(fmaxf(acc[nt][0] * invS, 0.f),
                                fmaxf(acc[nt][1] * invS, 0.f));
        float2 v1 = make_float2(fmaxf(acc[nt][2] * invS, 0.f),
                                fmaxf(acc[nt][3] * invS, 0.f));
        *(float2*)(out + (size_t)rowTop * DOUT + col)       = v0;
        *(float2*)(out + (size_t)(rowTop + 8) * DOUT + col) = v1;
    }
}

// ---------------------------------------------------------------------------
extern "C" void kernel_launch(void* const* d_in, const int* in_sizes, int n_in,
                              void* d_out, int out_size)
{
    const float* adj  = (const float*)d_in[0];   // [16384, 16384]
    const float* x    = (const float*)d_in[1];   // [16384, 128]
    const float* w    = (const float*)d_in[2];   // [128, 64]
    const float* bias = (const float*)d_in[3];   // [64]
    float* out = (float*)d_out;                  // [16384, 64]

    cudaFuncSetAttribute(gemm_kernel, cudaFuncAttributeMaxDynamicSharedMemorySize, SMEM_BYTES);

    transform_kernel<<<N_ROWS / 8, 256>>>(x, w, bias);
    gemm_kernel<<<N_ROWS / 128, 256, SMEM_BYTES>>>(adj, out);
}

// round 15
// speedup vs baseline: 2.7322x; 1.0167x over previous
#include <cuda_runtime.h>
#include <cuda_fp16.h>
#include <cstdint>

#define N_ROWS   16384
#define DIN      128
#define DOUT     64
#define KDIM     16384
#define MIN_NORM 1e-15f
#define ART_CLAMP (1.0f - 1e-7f)
#define MAXNORM  (1.0f - 4e-3f)

#define TK      64                  // k per chunk
#define NCH     (KDIM / TK)         // 256 chunks
#define APITCH  272                 // A smem row pitch (256B data + 16B pad)
#define ATILE   (128 * APITCH)      // 34816
#define BPITCH  144                 // B smem row pitch (128B data + 16B pad)
#define BTILE   (64 * BPITCH)       // 9216
#define STAGE   (ATILE + BTILE)     // 44032
#define BSTAGES 3
#define SMEM_BYTES (BSTAGES * STAGE)   // 132096

#define A_SCALE 16384.0f            // 2^14 exact; A in [0, 2^-14) -> [0,1)

// Tangent matrix, single fp16, K-major [DOUT][KDIM]
__device__ __half g_Bf[DOUT * KDIM];

// ---------------------------------------------------------------------------
// helpers
// ---------------------------------------------------------------------------
__device__ __forceinline__ uint32_t smem_u32(const void* p) {
    uint32_t a;
    asm("{ .reg .u64 t; cvta.to.shared.u64 t, %1; cvt.u32.u64 %0, t; }" : "=r"(a) : "l"(p));
    return a;
}
__device__ __forceinline__ void cp_async16(uint32_t dst, const void* src) {
    asm volatile(
        "{ .reg .u64 gp; cvta.to.global.u64 gp, %1;"
        " cp.async.cg.shared.global [%0], [gp], 16; }"
        :: "r"(dst), "l"(src) : "memory");
}
#define CP_COMMIT()  asm volatile("cp.async.commit_group;" ::: "memory")
#define CP_WAIT1()   asm volatile("cp.async.wait_group 1;" ::: "memory")
#define CP_WAIT0()   asm volatile("cp.async.wait_group 0;" ::: "memory")

__device__ __forceinline__ void ldsm4(uint32_t addr, uint32_t* r) {
    asm volatile("ldmatrix.sync.aligned.m8n8.x4.shared.b16 {%0,%1,%2,%3}, [%4];"
                 : "=r"(r[0]), "=r"(r[1]), "=r"(r[2]), "=r"(r[3]) : "r"(addr));
}
__device__ __forceinline__ void mma_f16(float* c, const uint32_t* a,
                                        uint32_t b0, uint32_t b1) {
    asm volatile(
        "mma.sync.aligned.m16n8k16.row.col.f32.f16.f16.f32 "
        "{%0,%1,%2,%3}, {%4,%5,%6,%7}, {%8,%9}, {%0,%1,%2,%3};"
        : "+f"(c[0]), "+f"(c[1]), "+f"(c[2]), "+f"(c[3])
        : "r"(a[0]), "r"(a[1]), "r"(a[2]), "r"(a[3]), "r"(b0), "r"(b1));
}
__device__ __forceinline__ float wsum(float v) {
#pragma unroll
    for (int o = 16; o > 0; o >>= 1) v += __shfl_xor_sync(0xffffffffu, v, o);
    return v;
}
// scale by A_SCALE and convert one float2 -> fp16x2 (normal range)
__device__ __forceinline__ uint32_t cvt2(float2 f) {
    __half2 h = __floats2half2_rn(f.x * A_SCALE, f.y * A_SCALE);
    return *(const uint32_t*)&h;
}

// ---------------------------------------------------------------------------
// Kernel A: hyperbolic transform -> tangent -> single fp16, K-major transposed.
// (unchanged, proven)
// ---------------------------------------------------------------------------
__global__ __launch_bounds__(256) void transform_kernel(
    const float* __restrict__ X,
    const float* __restrict__ W,
    const float* __restrict__ bias)
{
    __shared__ float2 sW2[DIN * 32];   // [k][t] = (W[k][t], W[k][t+32])

    const int tid = threadIdx.x;
    for (int i = tid; i < DIN * 32; i += 256) {
        const int k = i >> 5, t = i & 31;
        sW2[i] = make_float2(W[k * DOUT + t], W[k * DOUT + t + 32]);
    }
    __syncthreads();

    const int w    = tid >> 5;
    const int lane = tid & 31;
    const int row  = blockIdx.x * 8 + w;

    // hyp_bias = proj(expmap0(bias))
    float b1 = bias[lane], b2v = bias[lane + 32];
    float b2 = wsum(b1 * b1 + b2v * b2v);
    float bn = fmaxf(sqrtf(b2), MIN_NORM);
    float tb = tanhf(bn) / bn;
    float e1 = tb * b1, e2v = tb * b2v;
    float e2 = wsum(e1 * e1 + e2v * e2v);
    float en = fmaxf(sqrtf(e2), MIN_NORM);
    float sc = (en > MAXNORM) ? (MAXNORM / en) : 1.f;
    float h1 = e1 * sc, h2v = e2v * sc;
    float h2 = wsum(h1 * h1 + h2v * h2v);

    float xr[4];
#pragma unroll
    for (int j = 0; j < 4; ++j) xr[j] = X[(size_t)row * DIN + lane + 32 * j];
    float x2 = wsum(xr[0] * xr[0] + xr[1] * xr[1] + xr[2] * xr[2] + xr[3] * xr[3]);

    float ma = 0.f, mb = 0.f;
#pragma unroll
    for (int j = 0; j < 4; ++j) {
#pragma unroll
        for (int l = 0; l < 32; ++l) {
            const float xv = __shfl_sync(0xffffffffu, xr[j], l);
            const float2 wv = sW2[(j * 32 + l) * 32 + lane];
            ma = fmaf(xv, wv.x, ma);
            mb = fmaf(xv, wv.y, mb);
        }
    }

    float m2 = wsum(ma * ma + mb * mb);
    float xn = fmaxf(sqrtf(x2), MIN_NORM);
    float mn = fmaxf(sqrtf(m2), MIN_NORM);

    float artx = atanhf(fminf(xn, ART_CLAMP));
    float tf   = tanhf(mn / xn * artx) / mn;
    float r1 = tf * ma, r2v = tf * mb;
    if (m2 == 0.f) { r1 = 0.f; r2v = 0.f; }

    float r2 = wsum(r1 * r1 + r2v * r2v);
    float rh = wsum(r1 * h1 + r2v * h2v);
    float al  = 1.f + 2.f * rh + h2;
    float den = fmaxf(1.f + 2.f * rh + r2 * h2, MIN_NORM);
    float p1  = (al * r1  + (1.f - r2) * h1)  / den;
    float p2v = (al * r2v + (1.f - r2) * h2v) / den;

    float p2 = wsum(p1 * p1 + p2v * p2v);
    float pn = fmaxf(sqrtf(p2), MIN_NORM);
    if (pn > MAXNORM) {
        float s = MAXNORM / pn;
        p1 *= s; p2v *= s; pn = MAXNORM;
    }

    float lf = atanhf(fminf(pn, ART_CLAMP)) / pn;
    g_Bf[(size_t)lane * KDIM + row]        = __float2half(lf * p1);
    g_Bf[(size_t)(lane + 32) * KDIM + row] = __float2half(lf * p2v);
}

// ---------------------------------------------------------------------------
// Kernel B: out = relu(A @ T), both operands single fp16 (A scaled 2^14).
// 128 CTAs x 512 thr (16 warps = 8 m-groups x 2 k-halves), M128/N64/K-chunk 64.
// A+B staged via 3-stage cp.async; each warp touches only its k32 half.
// k-half partials reduced via smem at epilogue (R7-proven layout).
// ---------------------------------------------------------------------------
__global__ __launch_bounds__(512, 1) void gemm_kernel(
    const float* __restrict__ A,
    float* __restrict__ out)
{
    extern __shared__ __align__(128) char sm[];   // [stage][A(34816) | B(9216)]

    const int tid   = threadIdx.x;
    const int w     = tid >> 5;
    const int lane  = tid & 31;
    const int g     = lane >> 2;
    const int t4    = lane & 3;
    const int mg    = w >> 1;       // m-group 0..7
    const int khalf = w & 1;        // k32 half of each chunk
    const int m0    = blockIdx.x * 128;

    const uint32_t sb0 = smem_u32(sm);

    // cp.async mappings (fully coalesced, 5 x 16B per thread per stage)
    const int rA0 = tid >> 4, kcA = tid & 15;    // A: row rA0+32j (j<4), 16B chunk kcA
    const int rB0 = tid >> 3, kcB = tid & 7;     // B: row rB0, 16B chunk kcB (1 per thread)
    const float*  srcA0 = A + (size_t)(m0 + rA0) * KDIM + kcA * 4;
    const __half* srcB0 = g_Bf + (size_t)rB0 * KDIM + kcB * 8;
    const uint32_t dstA0 = (uint32_t)(rA0 * APITCH + kcA * 16);
    const uint32_t dstB0 = (uint32_t)(ATILE + rB0 * BPITCH + kcB * 16);

    // A LDS offsets (byte): rows mg*16+g (+8); khalf selects k32 (128B)
    const uint32_t aRow0 = (uint32_t)((mg * 16 + g) * APITCH + khalf * 128 + 8 * t4);
    const uint32_t aRow1 = aRow0 + 8 * APITCH;

    // ldmatrix lane offset within B tile (+ khalf selects k32 = 64B)
    const uint32_t lmOff = (uint32_t)(ATILE + (lane & 7) * BPITCH + (lane >> 3) * 16
                                      + khalf * 64);

    float acc[8][4];
#pragma unroll
    for (int i = 0; i < 8; ++i)
#pragma unroll
        for (int j = 0; j < 4; ++j) acc[i][j] = 0.f;

    // prologue: stages 0,1
#pragma unroll
    for (int s = 0; s < 2; ++s) {
        const int kb = s * TK;
        const uint32_t db = sb0 + (uint32_t)(s * STAGE);
#pragma unroll
        for (int j = 0; j < 4; ++j)
            cp_async16(db + dstA0 + (uint32_t)(j * 32 * APITCH),
                       srcA0 + (size_t)j * 32 * KDIM + kb);
        cp_async16(db + dstB0, srcB0 + kb);
        CP_COMMIT();
    }

    uint32_t ahF[8];
    uint32_t bf[8][4];

    for (int i = 0; i < NCH; ++i) {
        const int s = i % BSTAGES;

        if (i < NCH - 1) { CP_WAIT1(); } else { CP_WAIT0(); }
        __syncthreads();

        // issue stage i+2 (slot consumed at chunk i-1; barrier above makes it safe)
        if (i + 2 < NCH) {
            const int kb = (i + 2) * TK;
            const uint32_t db = sb0 + (uint32_t)(((i + 2) % BSTAGES) * STAGE);
#pragma unroll
            for (int j = 0; j < 4; ++j)
                cp_async16(db + dstA0 + (uint32_t)(j * 32 * APITCH),
                           srcA0 + (size_t)j * 32 * KDIM + kb);
            cp_async16(db + dstB0, srcB0 + kb);
            CP_COMMIT();
        }

        // build A fragments for this warp's k32: LDS float2 -> scale + cvt
        const char* stg = sm + (size_t)s * STAGE;
#pragma unroll
        for (int kf = 0; kf < 2; ++kf) {
            const uint32_t c = (uint32_t)(kf * 64);
            ahF[kf * 4 + 0] = cvt2(*(const float2*)(stg + aRow0 + c));        // (g,   k)
            ahF[kf * 4 + 1] = cvt2(*(const float2*)(stg + aRow1 + c));        // (g+8, k)
            ahF[kf * 4 + 2] = cvt2(*(const float2*)(stg + aRow0 + c + 32));   // (g,   k+8)
            ahF[kf * 4 + 3] = cvt2(*(const float2*)(stg + aRow1 + c + 32));   // (g+8, k+8)
        }

        const uint32_t bBase = sb0 + (uint32_t)(s * STAGE) + lmOff;

        // all ldsm first, then nt-major bursts (acc reuse distance 8)
#pragma unroll
        for (int nt = 0; nt < 8; ++nt)
            ldsm4(bBase + (uint32_t)(nt * 8 * BPITCH), bf[nt]);
#pragma unroll
        for (int nt = 0; nt < 8; ++nt) mma_f16(acc[nt], ahF,     bf[nt][0], bf[nt][1]);
#pragma unroll
        for (int nt = 0; nt < 8; ++nt) mma_f16(acc[nt], ahF + 4, bf[nt][2], bf[nt][3]);
    }

    // k-half reduction via smem (reuses pipeline buffers), then relu + store
    __syncthreads();
    float* red = (float*)sm;
    if (khalf == 1) {
        float* dst = red + (size_t)mg * 1024 + lane * 32;
#pragma unroll
        for (int nt = 0; nt < 8; ++nt)
#pragma unroll
            for (int j = 0; j < 4; ++j) dst[nt * 4 + j] = acc[nt][j];
    }
    __syncthreads();
    if (khalf == 0) {
        const float invS = 1.f / A_SCALE;
        const float* src = red + (size_t)mg * 1024 + lane * 32;
        const int rowTop = m0 + mg * 16 + g;
#pragma unroll
        for (int nt = 0; nt < 8; ++nt) {
            const int col = nt * 8 + t4 * 2;
            float2 v0 = make_float2(fmaxf((acc[nt][0] + src[nt * 4 + 0]) * invS, 0.f),
                                    fmaxf((acc[nt][1] + src[nt * 4 + 1]) * invS, 0.f));
            float2 v1 = make_float2(fmaxf((acc[nt][2] + src[nt * 4 + 2]) * invS, 0.f),
                                    fmaxf((acc[nt][3] + src[nt * 4 + 3]) * invS, 0.f));
            *(float2*)(out + (size_t)rowTop * DOUT + col)       = v0;
            *(float2*)(out + (size_t)(rowTop + 8) * DOUT + col) = v1;
        }
    }
}

// ---------------------------------------------------------------------------
extern "C" void kernel_launch(void* const* d_in, const int* in_sizes, int n_in,
                              void* d_out, int out_size)
{
    const float* adj  = (const float*)d_in[0];   // [16384, 16384]
    const float* x    = (const float*)d_in[1];   // [16384, 128]
    const float* w    = (const float*)d_in[2];   // [128, 64]
    const float* bias = (const float*)d_in[3];   // [64]
    float* out = (float*)d_out;                  // [16384, 64]

    cudaFuncSetAttribute(gemm_kernel, cudaFuncAttributeMaxDynamicSharedMemorySize, SMEM_BYTES);

    transform_kernel<<<N_ROWS / 8, 256>>>(x, w, bias);
    gemm_kernel<<<N_ROWS / 128, 512, SMEM_BYTES>>>(adj, out);
}